// round 4
// baseline (speedup 1.0000x reference)
#include <cuda_runtime.h>

#define NMAX   50000
#define EMAX   800000
#define D      96
#define D4     24    // D/4 float4 per row

// ---------------- scratch (device globals; no allocation allowed) ----------
__device__ float  g_pool[NMAX * D];             // pooled features (19.2 MB)
__device__ int    g_deg[NMAX];
__device__ int    g_rowptr[NMAX];
__device__ int    g_cursor[NMAX];
__device__ int    g_eidx[EMAX];                 // src index per CSR slot
__device__ float  g_sum[D];
__device__ float  g_sumsq[D];

// ---------------- K0: zero degree counters + BN accumulators ---------------
__global__ void zero_kernel(int n) {
    int i = blockIdx.x * blockDim.x + threadIdx.x;
    if (i < D) { g_sum[i] = 0.f; g_sumsq[i] = 0.f; }
    if (i < n) g_deg[i] = 0;
}

// ---------------- K1: histogram of dst (4 edges / thread for MLP) ----------
__global__ void hist_kernel(const int* __restrict__ dst, int E) {
    int base = (blockIdx.x * blockDim.x + threadIdx.x) * 4;
    #pragma unroll
    for (int j = 0; j < 4; j++) {
        int e = base + j;
        if (e < E) atomicAdd(&g_deg[dst[e]], 1);
    }
}

// ---------------- K2: exclusive scan -> rowptr, cursor (1 block) ------------
__global__ void scan_kernel(int n) {
    __shared__ int tmp[1024];
    const int tid = threadIdx.x;
    const int ch  = (n + 1023) >> 10;
    const int st  = tid * ch;
    const int en  = min(st + ch, n);

    int local = 0;
    for (int j = st; j < en; j++) local += g_deg[j];

    tmp[tid] = local;
    __syncthreads();
    for (int off = 1; off < 1024; off <<= 1) {
        int v = (tid >= off) ? tmp[tid - off] : 0;
        __syncthreads();
        tmp[tid] += v;
        __syncthreads();
    }
    int run = tmp[tid] - local;   // exclusive prefix
    for (int j = st; j < en; j++) {
        g_rowptr[j] = run;
        g_cursor[j] = run;
        run += g_deg[j];
    }
}

// ---------------- K3: fill CSR edge lists (4 edges / thread) ----------------
__global__ void fill_kernel(const int* __restrict__ src,
                            const int* __restrict__ dst, int E) {
    int base = (blockIdx.x * blockDim.x + threadIdx.x) * 4;
    int d[4], p[4], s[4];
    #pragma unroll
    for (int j = 0; j < 4; j++) {
        int e = base + j;
        if (e < E) { d[j] = dst[e]; s[j] = src[e]; }
    }
    #pragma unroll
    for (int j = 0; j < 4; j++) {
        int e = base + j;
        if (e < E) p[j] = atomicAdd(&g_cursor[d[j]], 1);
    }
    #pragma unroll
    for (int j = 0; j < 4; j++) {
        int e = base + j;
        if (e < E) g_eidx[p[j]] = s[j];
    }
}

// ---------------- K4: gather, one block per node ----------------------------
// 128 threads: stage edge list tile to SMEM, 96 col-threads accumulate
// scalars with 4-deep independent loads; epilogue adds (1+eps)*feat.
__global__ __launch_bounds__(128, 12)
void gather_kernel(const float* __restrict__ feat,
                   const float* __restrict__ eps, int n) {
    __shared__ int s_e[128];
    const int node = blockIdx.x;
    const int tid  = threadIdx.x;
    const int st   = g_rowptr[node];
    const int dg   = g_deg[node];

    float acc = 0.f;
    for (int base = 0; base < dg; base += 128) {
        int cnt = min(128, dg - base);
        __syncthreads();
        if (tid < cnt) s_e[tid] = g_eidx[st + base + tid];
        __syncthreads();
        if (tid < D) {
            int k = 0;
            for (; k + 4 <= cnt; k += 4) {
                int i0 = s_e[k], i1 = s_e[k+1], i2 = s_e[k+2], i3 = s_e[k+3];
                float v0 = __ldg(feat + i0 * D + tid);
                float v1 = __ldg(feat + i1 * D + tid);
                float v2 = __ldg(feat + i2 * D + tid);
                float v3 = __ldg(feat + i3 * D + tid);
                acc += (v0 + v1) + (v2 + v3);
            }
            for (; k < cnt; k++)
                acc += __ldg(feat + s_e[k] * D + tid);
        }
    }
    if (tid < D) {
        float s = 1.0f + __ldg(eps);
        g_pool[node * D + tid] = fmaf(s, __ldg(feat + node * D + tid), acc);
    }
}

// ---------------- K5: fused  h2 = relu(pooled@W1+b1)@W2+b2  + BN stats ------
#define TM 128
#define AS 100   // padded row stride for A tile

__global__ __launch_bounds__(256, 2)
void mlp_kernel(const float* __restrict__ W1, const float* __restrict__ b1,
                const float* __restrict__ W2, const float* __restrict__ b2,
                float* __restrict__ out, int n) {
    extern __shared__ float smem[];
    float* As    = smem;                 // TM * AS
    float* Ws    = smem + TM * AS;       // 96*96
    float* s_sum = Ws + D * D;           // 96
    float* s_sq  = s_sum + D;            // 96

    const int tid = threadIdx.x;
    const int tx  = tid & 7;
    const int ty  = tid >> 3;
    const int rb  = blockIdx.x * TM;

    if (tid < D) { s_sum[tid] = 0.f; s_sq[tid] = 0.f; }

    for (int i = tid; i < TM * D4; i += 256) {
        int r  = i / D4;
        int c4 = i - r * D4;
        float4 v = make_float4(0.f, 0.f, 0.f, 0.f);
        if (rb + r < n) v = *(const float4*)(g_pool + (rb + r) * D + c4 * 4);
        *(float4*)(As + r * AS + c4 * 4) = v;
    }
    for (int i = tid; i < (D * D) / 4; i += 256)
        ((float4*)Ws)[i] = ((const float4*)W1)[i];
    __syncthreads();

    float acc[4][12];
    #pragma unroll
    for (int r = 0; r < 4; r++)
        #pragma unroll
        for (int c = 0; c < 12; c++) acc[r][c] = 0.f;

    // ---- GEMM1 ----
    #pragma unroll 6
    for (int k4 = 0; k4 < D; k4 += 4) {
        float4 av[4];
        #pragma unroll
        for (int r = 0; r < 4; r++)
            av[r] = *(const float4*)(As + (ty * 4 + r) * AS + k4);
        #pragma unroll
        for (int kk = 0; kk < 4; kk++) {
            int k = k4 + kk;
            float4 w0 = *(const float4*)(Ws + k * D + tx * 12);
            float4 w1 = *(const float4*)(Ws + k * D + tx * 12 + 4);
            float4 w2 = *(const float4*)(Ws + k * D + tx * 12 + 8);
            float wv[12] = {w0.x,w0.y,w0.z,w0.w, w1.x,w1.y,w1.z,w1.w,
                            w2.x,w2.y,w2.z,w2.w};
            #pragma unroll
            for (int r = 0; r < 4; r++) {
                float a = (kk == 0) ? av[r].x : (kk == 1) ? av[r].y
                        : (kk == 2) ? av[r].z : av[r].w;
                #pragma unroll
                for (int c = 0; c < 12; c++)
                    acc[r][c] = fmaf(a, wv[c], acc[r][c]);
            }
        }
    }
    __syncthreads();

    #pragma unroll
    for (int c = 0; c < 12; c++) {
        float bb = __ldg(b1 + tx * 12 + c);
        #pragma unroll
        for (int r = 0; r < 4; r++)
            As[(ty * 4 + r) * AS + tx * 12 + c] = fmaxf(acc[r][c] + bb, 0.f);
    }
    for (int i = tid; i < (D * D) / 4; i += 256)
        ((float4*)Ws)[i] = ((const float4*)W2)[i];
    __syncthreads();

    #pragma unroll
    for (int r = 0; r < 4; r++)
        #pragma unroll
        for (int c = 0; c < 12; c++) acc[r][c] = 0.f;

    // ---- GEMM2 ----
    #pragma unroll 6
    for (int k4 = 0; k4 < D; k4 += 4) {
        float4 av[4];
        #pragma unroll
        for (int r = 0; r < 4; r++)
            av[r] = *(const float4*)(As + (ty * 4 + r) * AS + k4);
        #pragma unroll
        for (int kk = 0; kk < 4; kk++) {
            int k = k4 + kk;
            float4 w0 = *(const float4*)(Ws + k * D + tx * 12);
            float4 w1 = *(const float4*)(Ws + k * D + tx * 12 + 4);
            float4 w2 = *(const float4*)(Ws + k * D + tx * 12 + 8);
            float wv[12] = {w0.x,w0.y,w0.z,w0.w, w1.x,w1.y,w1.z,w1.w,
                            w2.x,w2.y,w2.z,w2.w};
            #pragma unroll
            for (int r = 0; r < 4; r++) {
                float a = (kk == 0) ? av[r].x : (kk == 1) ? av[r].y
                        : (kk == 2) ? av[r].z : av[r].w;
                #pragma unroll
                for (int c = 0; c < 12; c++)
                    acc[r][c] = fmaf(a, wv[c], acc[r][c]);
            }
        }
    }

    // ---- epilogue: +b2, store h2, reduce BN sums ----
    #pragma unroll
    for (int c = 0; c < 12; c++) {
        int col = tx * 12 + c;
        float bb = __ldg(b2 + col);
        float s = 0.f, s2 = 0.f;
        #pragma unroll
        for (int r = 0; r < 4; r++) {
            int row = rb + ty * 4 + r;
            float v = acc[r][c] + bb;
            if (row < n) {
                out[row * D + col] = v;
                s  += v;
                s2 += v * v;
            }
        }
        s  += __shfl_xor_sync(0xffffffffu, s, 8);
        s  += __shfl_xor_sync(0xffffffffu, s, 16);
        s2 += __shfl_xor_sync(0xffffffffu, s2, 8);
        s2 += __shfl_xor_sync(0xffffffffu, s2, 16);
        if ((tid & 31) < 8) {
            atomicAdd(&s_sum[col], s);
            atomicAdd(&s_sq[col], s2);
        }
    }
    __syncthreads();
    if (tid < D) {
        atomicAdd(&g_sum[tid],   s_sum[tid]);
        atomicAdd(&g_sumsq[tid], s_sq[tid]);
    }
}

// ---------------- K6: apply BN + ReLU (finalize fused per-block) ------------
__global__ void apply_kernel(const float* __restrict__ gamma,
                             const float* __restrict__ beta,
                             float invN, float4* __restrict__ out4, int n4) {
    __shared__ __align__(16) float sc[D];
    __shared__ __align__(16) float sh[D];
    int tid = threadIdx.x;
    if (tid < D) {
        float mean = g_sum[tid] * invN;
        float var  = g_sumsq[tid] * invN - mean * mean;
        float rstd = rsqrtf(var + 1e-5f);
        float s    = rstd * gamma[tid];
        sc[tid] = s;
        sh[tid] = beta[tid] - mean * s;
    }
    __syncthreads();

    int i = blockIdx.x * blockDim.x + tid;
    if (i >= n4) return;
    int c4 = i % D4;
    float4 h  = out4[i];
    float4 s4 = ((const float4*)sc)[c4];
    float4 h4 = ((const float4*)sh)[c4];
    h.x = fmaxf(fmaf(h.x, s4.x, h4.x), 0.f);
    h.y = fmaxf(fmaf(h.y, s4.y, h4.y), 0.f);
    h.z = fmaxf(fmaf(h.z, s4.z, h4.z), 0.f);
    h.w = fmaxf(fmaf(h.w, s4.w, h4.w), 0.f);
    out4[i] = h;
}

// ---------------------------------------------------------------------------
extern "C" void kernel_launch(void* const* d_in, const int* in_sizes, int n_in,
                              void* d_out, int out_size) {
    const float* feature = (const float*)d_in[0];
    const int*   src     = (const int*)d_in[1];
    const int*   dst     = (const int*)d_in[2];
    const float* W1      = (const float*)d_in[3];
    const float* b1      = (const float*)d_in[4];
    const float* W2      = (const float*)d_in[5];
    const float* b2      = (const float*)d_in[6];
    const float* gamma   = (const float*)d_in[7];
    const float* beta    = (const float*)d_in[8];
    const float* eps     = (const float*)d_in[9];
    float* out = (float*)d_out;

    const int n  = in_sizes[0] / D;     // 50000
    const int E  = in_sizes[1];         // 800000
    const int n4 = n * D4;

    zero_kernel<<<(n + 255) / 256, 256>>>(n);
    hist_kernel<<<(E / 4 + 255) / 256, 256>>>(dst, E);
    scan_kernel<<<1, 1024>>>(n);
    fill_kernel<<<(E / 4 + 255) / 256, 256>>>(src, dst, E);
    gather_kernel<<<n, 128>>>(feature, eps, n);

    const int SMEM = (TM * AS + D * D + 2 * D) * (int)sizeof(float); // 88832 B
    cudaFuncSetAttribute(mlp_kernel,
                         cudaFuncAttributeMaxDynamicSharedMemorySize, SMEM);
    mlp_kernel<<<(n + TM - 1) / TM, 256, SMEM>>>(W1, b1, W2, b2, out, n);

    apply_kernel<<<(n4 + 255) / 256, 256>>>(gamma, beta, 1.0f / (float)n,
                                            (float4*)out, n4);
}

// round 5
// speedup vs baseline: 1.6788x; 1.6788x over previous
#include <cuda_runtime.h>

#define NMAX   50000
#define D      96
#define D4     24    // D/4 float4 per row

// ---------------- scratch (device globals; no allocation allowed) ----------
__device__ float4 g_pool[NMAX * D4];            // pooled features (19.2 MB)
__device__ float  g_sum[D];
__device__ float  g_sumsq[D];

// ---------------- K1: pooled = (1+eps)*feature; zero BN accumulators -------
__global__ void init_kernel(const float4* __restrict__ feat,
                            const float* __restrict__ eps, int n4) {
    int i = blockIdx.x * blockDim.x + threadIdx.x;
    if (i < D) { g_sum[i] = 0.f; g_sumsq[i] = 0.f; }
    if (i >= n4) return;
    float s = 1.0f + eps[0];
    float4 v = feat[i];
    v.x *= s; v.y *= s; v.z *= s; v.w *= s;
    g_pool[i] = v;
}

// ---------------- K2: edge scatter: pooled[dst] += feature[src] ------------
// 8 threads per edge, 3 float4 chunks per thread:
//   chunks j, j+8, j+16 -> each load step is a contiguous 128B row segment
//   per warp-group, and per-thread ILP is 3 independent LDG/RED pairs.
__global__ void scatter_kernel(const float4* __restrict__ feat,
                               const int* __restrict__ src,
                               const int* __restrict__ dst, int total) {
    int i = blockIdx.x * blockDim.x + threadIdx.x;
    if (i >= total) return;
    int e = i >> 3;          // edge
    int j = i & 7;           // chunk lane 0..7
    int s = __ldg(src + e);
    int d = __ldg(dst + e);
    const float4* fp = feat + (long)s * D4 + j;
    float4* pp = g_pool + (long)d * D4 + j;
    float4 v0 = __ldg(fp);
    float4 v1 = __ldg(fp + 8);
    float4 v2 = __ldg(fp + 16);
    asm volatile("red.global.add.v4.f32 [%0], {%1,%2,%3,%4};"
                 :: "l"(pp), "f"(v0.x), "f"(v0.y), "f"(v0.z), "f"(v0.w) : "memory");
    asm volatile("red.global.add.v4.f32 [%0], {%1,%2,%3,%4};"
                 :: "l"(pp + 8), "f"(v1.x), "f"(v1.y), "f"(v1.z), "f"(v1.w) : "memory");
    asm volatile("red.global.add.v4.f32 [%0], {%1,%2,%3,%4};"
                 :: "l"(pp + 16), "f"(v2.x), "f"(v2.y), "f"(v2.z), "f"(v2.w) : "memory");
}

// ---------------- K3: fused  h2 = relu(pooled@W1+b1)@W2+b2  + BN stats -----
#define TM 128
#define AS 100   // padded row stride for A tile

__global__ __launch_bounds__(256, 2)
void mlp_kernel(const float* __restrict__ W1, const float* __restrict__ b1,
                const float* __restrict__ W2, const float* __restrict__ b2,
                float* __restrict__ out, int n) {
    extern __shared__ float smem[];
    float* As    = smem;                 // TM * AS
    float* Ws    = smem + TM * AS;       // 96*96
    float* s_sum = Ws + D * D;           // 96
    float* s_sq  = s_sum + D;            // 96

    const int tid = threadIdx.x;
    const int tx  = tid & 7;
    const int ty  = tid >> 3;
    const int rb  = blockIdx.x * TM;

    if (tid < D) { s_sum[tid] = 0.f; s_sq[tid] = 0.f; }

    for (int i = tid; i < TM * D4; i += 256) {
        int r  = i / D4;
        int c4 = i - r * D4;
        float4 v = make_float4(0.f, 0.f, 0.f, 0.f);
        if (rb + r < n) v = g_pool[(rb + r) * D4 + c4];
        *(float4*)(As + r * AS + c4 * 4) = v;
    }
    for (int i = tid; i < (D * D) / 4; i += 256)
        ((float4*)Ws)[i] = ((const float4*)W1)[i];
    __syncthreads();

    float acc[4][12];
    #pragma unroll
    for (int r = 0; r < 4; r++)
        #pragma unroll
        for (int c = 0; c < 12; c++) acc[r][c] = 0.f;

    // ---- GEMM1 ----
    #pragma unroll 6
    for (int k4 = 0; k4 < D; k4 += 4) {
        float4 av[4];
        #pragma unroll
        for (int r = 0; r < 4; r++)
            av[r] = *(const float4*)(As + (ty * 4 + r) * AS + k4);
        #pragma unroll
        for (int kk = 0; kk < 4; kk++) {
            int k = k4 + kk;
            float4 w0 = *(const float4*)(Ws + k * D + tx * 12);
            float4 w1 = *(const float4*)(Ws + k * D + tx * 12 + 4);
            float4 w2 = *(const float4*)(Ws + k * D + tx * 12 + 8);
            float wv[12] = {w0.x,w0.y,w0.z,w0.w, w1.x,w1.y,w1.z,w1.w,
                            w2.x,w2.y,w2.z,w2.w};
            #pragma unroll
            for (int r = 0; r < 4; r++) {
                float a = (kk == 0) ? av[r].x : (kk == 1) ? av[r].y
                        : (kk == 2) ? av[r].z : av[r].w;
                #pragma unroll
                for (int c = 0; c < 12; c++)
                    acc[r][c] = fmaf(a, wv[c], acc[r][c]);
            }
        }
    }
    __syncthreads();

    #pragma unroll
    for (int c = 0; c < 12; c++) {
        float bb = __ldg(b1 + tx * 12 + c);
        #pragma unroll
        for (int r = 0; r < 4; r++)
            As[(ty * 4 + r) * AS + tx * 12 + c] = fmaxf(acc[r][c] + bb, 0.f);
    }
    for (int i = tid; i < (D * D) / 4; i += 256)
        ((float4*)Ws)[i] = ((const float4*)W2)[i];
    __syncthreads();

    #pragma unroll
    for (int r = 0; r < 4; r++)
        #pragma unroll
        for (int c = 0; c < 12; c++) acc[r][c] = 0.f;

    // ---- GEMM2 ----
    #pragma unroll 6
    for (int k4 = 0; k4 < D; k4 += 4) {
        float4 av[4];
        #pragma unroll
        for (int r = 0; r < 4; r++)
            av[r] = *(const float4*)(As + (ty * 4 + r) * AS + k4);
        #pragma unroll
        for (int kk = 0; kk < 4; kk++) {
            int k = k4 + kk;
            float4 w0 = *(const float4*)(Ws + k * D + tx * 12);
            float4 w1 = *(const float4*)(Ws + k * D + tx * 12 + 4);
            float4 w2 = *(const float4*)(Ws + k * D + tx * 12 + 8);
            float wv[12] = {w0.x,w0.y,w0.z,w0.w, w1.x,w1.y,w1.z,w1.w,
                            w2.x,w2.y,w2.z,w2.w};
            #pragma unroll
            for (int r = 0; r < 4; r++) {
                float a = (kk == 0) ? av[r].x : (kk == 1) ? av[r].y
                        : (kk == 2) ? av[r].z : av[r].w;
                #pragma unroll
                for (int c = 0; c < 12; c++)
                    acc[r][c] = fmaf(a, wv[c], acc[r][c]);
            }
        }
    }

    // ---- epilogue: +b2, store h2, reduce BN sums ----
    #pragma unroll
    for (int c = 0; c < 12; c++) {
        int col = tx * 12 + c;
        float bb = __ldg(b2 + col);
        float s = 0.f, s2 = 0.f;
        #pragma unroll
        for (int r = 0; r < 4; r++) {
            int row = rb + ty * 4 + r;
            float v = acc[r][c] + bb;
            if (row < n) {
                out[row * D + col] = v;
                s  += v;
                s2 += v * v;
            }
        }
        s  += __shfl_xor_sync(0xffffffffu, s, 8);
        s  += __shfl_xor_sync(0xffffffffu, s, 16);
        s2 += __shfl_xor_sync(0xffffffffu, s2, 8);
        s2 += __shfl_xor_sync(0xffffffffu, s2, 16);
        if ((tid & 31) < 8) {
            atomicAdd(&s_sum[col], s);
            atomicAdd(&s_sq[col], s2);
        }
    }
    __syncthreads();
    if (tid < D) {
        atomicAdd(&g_sum[tid],   s_sum[tid]);
        atomicAdd(&g_sumsq[tid], s_sq[tid]);
    }
}

// ---------------- K4: apply BN + ReLU (finalize fused per-block) ------------
__global__ void apply_kernel(const float* __restrict__ gamma,
                             const float* __restrict__ beta,
                             float invN, float4* __restrict__ out4, int n4) {
    __shared__ __align__(16) float sc[D];
    __shared__ __align__(16) float sh[D];
    int tid = threadIdx.x;
    if (tid < D) {
        float mean = g_sum[tid] * invN;
        float var  = g_sumsq[tid] * invN - mean * mean;
        float rstd = rsqrtf(var + 1e-5f);
        float s    = rstd * gamma[tid];
        sc[tid] = s;
        sh[tid] = beta[tid] - mean * s;
    }
    __syncthreads();

    int i = blockIdx.x * blockDim.x + tid;
    if (i >= n4) return;
    int c4 = i % D4;
    float4 h  = out4[i];
    float4 s4 = ((const float4*)sc)[c4];
    float4 h4 = ((const float4*)sh)[c4];
    h.x = fmaxf(fmaf(h.x, s4.x, h4.x), 0.f);
    h.y = fmaxf(fmaf(h.y, s4.y, h4.y), 0.f);
    h.z = fmaxf(fmaf(h.z, s4.z, h4.z), 0.f);
    h.w = fmaxf(fmaf(h.w, s4.w, h4.w), 0.f);
    out4[i] = h;
}

// ---------------------------------------------------------------------------
extern "C" void kernel_launch(void* const* d_in, const int* in_sizes, int n_in,
                              void* d_out, int out_size) {
    const float* feature = (const float*)d_in[0];
    const int*   src     = (const int*)d_in[1];
    const int*   dst     = (const int*)d_in[2];
    const float* W1      = (const float*)d_in[3];
    const float* b1      = (const float*)d_in[4];
    const float* W2      = (const float*)d_in[5];
    const float* b2      = (const float*)d_in[6];
    const float* gamma   = (const float*)d_in[7];
    const float* beta    = (const float*)d_in[8];
    const float* eps     = (const float*)d_in[9];
    float* out = (float*)d_out;

    const int n  = in_sizes[0] / D;     // 50000
    const int E  = in_sizes[1];         // 800000
    const int n4 = n * D4;

    init_kernel<<<(n4 + 255) / 256, 256>>>((const float4*)feature, eps, n4);

    int total = E * 8;                   // 6.4M threads, 3 chunks each
    scatter_kernel<<<(total + 255) / 256, 256>>>((const float4*)feature,
                                                 src, dst, total);

    const int SMEM = (TM * AS + D * D + 2 * D) * (int)sizeof(float); // 88832 B
    cudaFuncSetAttribute(mlp_kernel,
                         cudaFuncAttributeMaxDynamicSharedMemorySize, SMEM);
    mlp_kernel<<<(n + TM - 1) / TM, 256, SMEM>>>(W1, b1, W2, b2, out, n);

    apply_kernel<<<(n4 + 255) / 256, 256>>>(gamma, beta, 1.0f / (float)n,
                                            (float4*)out, n4);
}